// round 1
// baseline (speedup 1.0000x reference)
#include <cuda_runtime.h>
#include <math.h>

#define BATCH 4
#define SEQ   2048
#define DIM   1024
#define NH    16
#define HD    64
#define MTOK  (BATCH*SEQ)        // 8192
#define SCALE 0.125f             // 1/sqrt(64)

// Scratch (allocation-free: __device__ globals)
__device__ float g_q[BATCH*NH*SEQ*HD];     // 32 MB
__device__ float g_k[BATCH*NH*SEQ*HD];     // 32 MB
__device__ float g_v[BATCH*NH*SEQ*HD];     // 32 MB
__device__ float g_attn[MTOK*DIM];         // 32 MB

// ---------------------------------------------------------------------------
// SGEMM core: 128x128 tile, BK=8, 256 threads, 8x8 per-thread register tile.
// A row-major [M,K], B row-major [K,N].
// ---------------------------------------------------------------------------
#define BM 128
#define BN 128
#define BK 8
#define TM 8
#define TN 8

// QKV projection: C = x @ w_qkv + b_qkv, scattered into g_q/g_k/g_v (B,H,S,Hd)
__global__ void __launch_bounds__(256) sgemm_qkv(
    const float* __restrict__ A, const float* __restrict__ Bm,
    const float* __restrict__ bias)
{
    const int K = DIM, N = 3*DIM;
    __shared__ float As[BK][BM];
    __shared__ float Bs[BK][BN];

    int tid = threadIdx.x;
    int tx = tid & 15, ty = tid >> 4;
    int row0 = blockIdx.y * BM;
    int col0 = blockIdx.x * BN;

    int aRow = tid >> 1;            // 0..127
    int aCol = (tid & 1) * 4;       // 0 or 4
    int bRow = tid >> 5;            // 0..7
    int bCol = (tid & 31) * 4;      // 0..124

    float acc[TM][TN];
    #pragma unroll
    for (int i = 0; i < TM; i++)
        #pragma unroll
        for (int j = 0; j < TN; j++) acc[i][j] = 0.f;

    for (int k0 = 0; k0 < K; k0 += BK) {
        float4 av = *(const float4*)&A[(size_t)(row0 + aRow)*K + k0 + aCol];
        As[aCol+0][aRow] = av.x;
        As[aCol+1][aRow] = av.y;
        As[aCol+2][aRow] = av.z;
        As[aCol+3][aRow] = av.w;
        float4 bv = *(const float4*)&Bm[(size_t)(k0 + bRow)*N + col0 + bCol];
        *(float4*)&Bs[bRow][bCol] = bv;
        __syncthreads();

        #pragma unroll
        for (int kk = 0; kk < BK; kk++) {
            float ar[TM], br[TN];
            #pragma unroll
            for (int i = 0; i < TM; i++) ar[i] = As[kk][ty*TM + i];
            #pragma unroll
            for (int j = 0; j < TN; j++) br[j] = Bs[kk][tx*TN + j];
            #pragma unroll
            for (int i = 0; i < TM; i++)
                #pragma unroll
                for (int j = 0; j < TN; j++)
                    acc[i][j] = fmaf(ar[i], br[j], acc[i][j]);
        }
        __syncthreads();
    }

    #pragma unroll
    for (int i = 0; i < TM; i++) {
        int row = row0 + ty*TM + i;
        int b   = row >> 11;          // /SEQ
        int s   = row & 2047;
        #pragma unroll
        for (int j = 0; j < TN; j++) {
            int col = col0 + tx*TN + j;
            float v = acc[i][j] + bias[col];
            int three = col >> 10;
            int rem   = col & 1023;
            int h     = rem >> 6;
            int hd    = rem & 63;
            size_t dst = ((size_t)(b*NH + h)*SEQ + s)*HD + hd;
            if (three == 0)      g_q[dst] = v;
            else if (three == 1) g_k[dst] = v;
            else                 g_v[dst] = v;
        }
    }
}

// Output projection: d_out = g_attn @ w_out + b_out
__global__ void __launch_bounds__(256) sgemm_out(
    const float* __restrict__ Bm, const float* __restrict__ bias,
    float* __restrict__ C)
{
    const int K = DIM, N = DIM;
    const float* A = g_attn;
    __shared__ float As[BK][BM];
    __shared__ float Bs[BK][BN];

    int tid = threadIdx.x;
    int tx = tid & 15, ty = tid >> 4;
    int row0 = blockIdx.y * BM;
    int col0 = blockIdx.x * BN;

    int aRow = tid >> 1;
    int aCol = (tid & 1) * 4;
    int bRow = tid >> 5;
    int bCol = (tid & 31) * 4;

    float acc[TM][TN];
    #pragma unroll
    for (int i = 0; i < TM; i++)
        #pragma unroll
        for (int j = 0; j < TN; j++) acc[i][j] = 0.f;

    for (int k0 = 0; k0 < K; k0 += BK) {
        float4 av = *(const float4*)&A[(size_t)(row0 + aRow)*K + k0 + aCol];
        As[aCol+0][aRow] = av.x;
        As[aCol+1][aRow] = av.y;
        As[aCol+2][aRow] = av.z;
        As[aCol+3][aRow] = av.w;
        float4 bv = *(const float4*)&Bm[(size_t)(k0 + bRow)*N + col0 + bCol];
        *(float4*)&Bs[bRow][bCol] = bv;
        __syncthreads();

        #pragma unroll
        for (int kk = 0; kk < BK; kk++) {
            float ar[TM], br[TN];
            #pragma unroll
            for (int i = 0; i < TM; i++) ar[i] = As[kk][ty*TM + i];
            #pragma unroll
            for (int j = 0; j < TN; j++) br[j] = Bs[kk][tx*TN + j];
            #pragma unroll
            for (int i = 0; i < TM; i++)
                #pragma unroll
                for (int j = 0; j < TN; j++)
                    acc[i][j] = fmaf(ar[i], br[j], acc[i][j]);
        }
        __syncthreads();
    }

    #pragma unroll
    for (int i = 0; i < TM; i++) {
        int row = row0 + ty*TM + i;
        #pragma unroll
        for (int j = 0; j < TN; j++) {
            int col = col0 + tx*TN + j;
            C[(size_t)row*N + col] = acc[i][j] + bias[col];
        }
    }
}

// ---------------------------------------------------------------------------
// Fused attention (flash-style, fp32): block = 64 queries of one (b,h),
// iterate key tiles of 64. Online softmax. 256 threads: thread owns a
// 4-row x 4-col tile of the 64x64 score block; 16 threads per row-group.
// ---------------------------------------------------------------------------
#define QT 64
#define KT 64
#define PITCH 65   // 2-way-conflict padding

__global__ void __launch_bounds__(256) attn_kernel()
{
    extern __shared__ float sm[];
    float* Qs = sm;                    // [64][PITCH]
    float* Ks = Qs + QT*PITCH;         // [64][PITCH]
    float* Vs = Ks + KT*PITCH;         // [64][PITCH]
    float* Ps = Vs + KT*PITCH;         // [64][PITCH]

    int tid = threadIdx.x;
    int b = blockIdx.z;
    int h = blockIdx.y;
    int q0 = blockIdx.x * QT;

    const float* qptr = g_q + ((size_t)(b*NH + h)*SEQ)*HD;
    const float* kptr = g_k + ((size_t)(b*NH + h)*SEQ)*HD;
    const float* vptr = g_v + ((size_t)(b*NH + h)*SEQ)*HD;

    // load Q tile (scaled by 1/sqrt(Hd)): 64x64 floats = 1024 float4s
    #pragma unroll
    for (int it = 0; it < 4; it++) {
        int e = tid + it*256;          // 0..1023
        int r = e >> 4;
        int c4 = (e & 15) * 4;
        float4 v = *(const float4*)&qptr[(size_t)(q0 + r)*HD + c4];
        Qs[r*PITCH + c4 + 0] = v.x * SCALE;
        Qs[r*PITCH + c4 + 1] = v.y * SCALE;
        Qs[r*PITCH + c4 + 2] = v.z * SCALE;
        Qs[r*PITCH + c4 + 3] = v.w * SCALE;
    }

    int r0 = (tid >> 4) * 4;           // row group base (0..60)
    int c0 = (tid & 15) * 4;           // col base (0..60)

    float m_i[4], l_i[4], o[4][4];
    #pragma unroll
    for (int i = 0; i < 4; i++) {
        m_i[i] = -INFINITY; l_i[i] = 0.f;
        #pragma unroll
        for (int j = 0; j < 4; j++) o[i][j] = 0.f;
    }

    __syncthreads();

    for (int kt = 0; kt < SEQ; kt += KT) {
        // load K and V tiles
        #pragma unroll
        for (int it = 0; it < 4; it++) {
            int e = tid + it*256;
            int r = e >> 4;
            int c4 = (e & 15) * 4;
            float4 kv = *(const float4*)&kptr[(size_t)(kt + r)*HD + c4];
            Ks[r*PITCH + c4 + 0] = kv.x;
            Ks[r*PITCH + c4 + 1] = kv.y;
            Ks[r*PITCH + c4 + 2] = kv.z;
            Ks[r*PITCH + c4 + 3] = kv.w;
            float4 vv = *(const float4*)&vptr[(size_t)(kt + r)*HD + c4];
            Vs[r*PITCH + c4 + 0] = vv.x;
            Vs[r*PITCH + c4 + 1] = vv.y;
            Vs[r*PITCH + c4 + 2] = vv.z;
            Vs[r*PITCH + c4 + 3] = vv.w;
        }
        __syncthreads();

        // scores s[4][4] = Q(rows r0..) . K(rows c0..)
        float s[4][4];
        #pragma unroll
        for (int i = 0; i < 4; i++)
            #pragma unroll
            for (int j = 0; j < 4; j++) s[i][j] = 0.f;

        #pragma unroll 8
        for (int d = 0; d < HD; d++) {
            float qa[4], kb[4];
            #pragma unroll
            for (int i = 0; i < 4; i++) qa[i] = Qs[(r0+i)*PITCH + d];
            #pragma unroll
            for (int j = 0; j < 4; j++) kb[j] = Ks[(c0+j)*PITCH + d];
            #pragma unroll
            for (int i = 0; i < 4; i++)
                #pragma unroll
                for (int j = 0; j < 4; j++)
                    s[i][j] = fmaf(qa[i], kb[j], s[i][j]);
        }

        // online softmax update (row reduction over 16 lanes of the row group)
        #pragma unroll
        for (int i = 0; i < 4; i++) {
            float mloc = s[i][0];
            mloc = fmaxf(mloc, s[i][1]);
            mloc = fmaxf(mloc, s[i][2]);
            mloc = fmaxf(mloc, s[i][3]);
            #pragma unroll
            for (int off = 8; off >= 1; off >>= 1)
                mloc = fmaxf(mloc, __shfl_xor_sync(0xffffffffu, mloc, off));
            float m_new = fmaxf(m_i[i], mloc);
            float alpha = __expf(m_i[i] - m_new);
            float lsum = 0.f;
            #pragma unroll
            for (int j = 0; j < 4; j++) {
                float p = __expf(s[i][j] - m_new);
                s[i][j] = p;                    // reuse as P
                lsum += p;
            }
            #pragma unroll
            for (int off = 8; off >= 1; off >>= 1)
                lsum += __shfl_xor_sync(0xffffffffu, lsum, off);
            l_i[i] = l_i[i] * alpha + lsum;
            m_i[i] = m_new;
            #pragma unroll
            for (int j = 0; j < 4; j++) o[i][j] *= alpha;
        }

        // stage P for the PV product
        #pragma unroll
        for (int i = 0; i < 4; i++)
            #pragma unroll
            for (int j = 0; j < 4; j++)
                Ps[(r0+i)*PITCH + (c0+j)] = s[i][j];
        __syncthreads();

        // o += P @ V  (thread owns rows r0.., output dims c0..)
        #pragma unroll 8
        for (int kk = 0; kk < KT; kk++) {
            float pa[4], vb[4];
            #pragma unroll
            for (int i = 0; i < 4; i++) pa[i] = Ps[(r0+i)*PITCH + kk];
            #pragma unroll
            for (int j = 0; j < 4; j++) vb[j] = Vs[kk*PITCH + (c0+j)];
            #pragma unroll
            for (int i = 0; i < 4; i++)
                #pragma unroll
                for (int j = 0; j < 4; j++)
                    o[i][j] = fmaf(pa[i], vb[j], o[i][j]);
        }
        __syncthreads();   // before next tile overwrites Ks/Vs
    }

    // write normalized output in (B,S,D) layout for the final GEMM
    #pragma unroll
    for (int i = 0; i < 4; i++) {
        float inv_l = 1.f / l_i[i];
        #pragma unroll
        for (int j = 0; j < 4; j++) {
            size_t dst = ((size_t)b*SEQ + q0 + r0 + i)*DIM + h*HD + c0 + j;
            g_attn[dst] = o[i][j] * inv_l;
        }
    }
}

// ---------------------------------------------------------------------------
extern "C" void kernel_launch(void* const* d_in, const int* in_sizes, int n_in,
                              void* d_out, int out_size)
{
    const float* x      = (const float*)d_in[0];
    const float* w_qkv  = (const float*)d_in[1];
    const float* b_qkv  = (const float*)d_in[2];
    const float* w_out  = (const float*)d_in[3];
    const float* b_out  = (const float*)d_in[4];
    float* out = (float*)d_out;

    // 1) QKV projection + scatter
    dim3 g1(3*DIM / BN, MTOK / BM);
    sgemm_qkv<<<g1, 256>>>(x, w_qkv, b_qkv);

    // 2) fused attention
    size_t smem = (size_t)4 * QT * PITCH * sizeof(float);  // 66560 B
    cudaFuncSetAttribute(attn_kernel,
                         cudaFuncAttributeMaxDynamicSharedMemorySize, (int)smem);
    dim3 g2(SEQ / QT, NH, BATCH);
    attn_kernel<<<g2, 256, smem>>>();

    // 3) output projection
    dim3 g3(DIM / BN, MTOK / BM);
    sgemm_out<<<g3, 256>>>(w_out, b_out, out);
}

// round 2
// speedup vs baseline: 2.6764x; 2.6764x over previous
#include <cuda_runtime.h>
#include <math.h>
#include <stdint.h>

#define BATCH 4
#define SEQ   2048
#define DIM   1024
#define NH    16
#define HD    64
#define MTOK  (BATCH*SEQ)        // 8192
#define SCALE 0.125f             // 1/sqrt(64)

// Scratch (allocation-free: __device__ globals)
__device__ float g_q[BATCH*NH*SEQ*HD];     // 32 MB
__device__ float g_k[BATCH*NH*SEQ*HD];     // 32 MB
__device__ float g_v[BATCH*NH*SEQ*HD];     // 32 MB
__device__ float g_attn[MTOK*DIM];         // 32 MB

// ---------------------------------------------------------------------------
// tf32 helpers
// ---------------------------------------------------------------------------
__device__ __forceinline__ uint32_t tf32cvt(float x) {
    uint32_t r;
    asm("cvt.rna.tf32.f32 %0, %1;" : "=r"(r) : "f"(x));
    return r;
}

__device__ __forceinline__ void mma_tf32(float c[4],
                                         const uint32_t a[4],
                                         const uint32_t b[2]) {
    asm volatile(
        "mma.sync.aligned.m16n8k8.row.col.f32.tf32.tf32.f32 "
        "{%0,%1,%2,%3},{%4,%5,%6,%7},{%8,%9},{%0,%1,%2,%3};"
        : "+f"(c[0]), "+f"(c[1]), "+f"(c[2]), "+f"(c[3])
        : "r"(a[0]), "r"(a[1]), "r"(a[2]), "r"(a[3]),
          "r"(b[0]), "r"(b[1]));
}

// ---------------------------------------------------------------------------
// tf32 MMA GEMM: 128x128 block tile, BK=16, 256 threads = 8 warps (2x4),
// each warp computes 64x32 via 4x4 m16n8k8 mma tiles.
// A row-major [M,K], B row-major [K,N].
// ---------------------------------------------------------------------------
#define GBM 128
#define GBN 128
#define GBK 16
#define APITCH 20    // 16 + 4  -> conflict-free a-frag loads
#define BPITCH 132   // 128 + 4 -> conflict-free b-frag loads

// Computes one 128x128 tile of acc = A@B (no epilogue). Caller does epilogue.
// acc layout: acc[mt][nt][{c0..c3}]
#define GEMM_CORE(A_, B_, K_, N_)                                              \
    __shared__ float As[GBM][APITCH];                                          \
    __shared__ float Bs[GBK][BPITCH];                                          \
    int tid  = threadIdx.x;                                                    \
    int lane = tid & 31;                                                       \
    int wid  = tid >> 5;                                                       \
    int wr   = wid >> 2;          /* 0..1 */                                   \
    int wc   = wid & 3;           /* 0..3 */                                   \
    int gid  = lane >> 2;         /* 0..7 */                                   \
    int q4   = lane & 3;          /* 0..3 */                                   \
    int row0 = blockIdx.y * GBM;                                               \
    int col0 = blockIdx.x * GBN;                                               \
    float acc[4][4][4];                                                        \
    _Pragma("unroll")                                                          \
    for (int mt = 0; mt < 4; mt++)                                             \
        _Pragma("unroll")                                                      \
        for (int nt = 0; nt < 4; nt++)                                         \
            _Pragma("unroll")                                                  \
            for (int e = 0; e < 4; e++) acc[mt][nt][e] = 0.f;                  \
    for (int k0 = 0; k0 < (K_); k0 += GBK) {                                   \
        _Pragma("unroll")                                                      \
        for (int i = 0; i < 2; i++) {                                          \
            int id = tid * 2 + i;              /* 0..511 */                    \
            int r  = id >> 2;                                                  \
            int cg = (id & 3) * 4;                                             \
            float4 v = *(const float4*)&(A_)[(size_t)(row0 + r) * (K_) + k0 + cg]; \
            *(float4*)&As[r][cg] = v;                                          \
        }                                                                      \
        _Pragma("unroll")                                                      \
        for (int i = 0; i < 2; i++) {                                          \
            int id = tid * 2 + i;                                              \
            int r  = id >> 5;                                                  \
            int c  = (id & 31) * 4;                                            \
            float4 v = *(const float4*)&(B_)[(size_t)(k0 + r) * (N_) + col0 + c]; \
            *(float4*)&Bs[r][c] = v;                                           \
        }                                                                      \
        __syncthreads();                                                       \
        _Pragma("unroll")                                                      \
        for (int ks = 0; ks < 2; ks++) {                                       \
            int kb = ks * 8;                                                   \
            uint32_t af[4][4], bf[4][2];                                       \
            _Pragma("unroll")                                                  \
            for (int mt = 0; mt < 4; mt++) {                                   \
                int m = wr * 64 + mt * 16 + gid;                               \
                int k = kb + q4;                                               \
                af[mt][0] = tf32cvt(As[m][k]);                                 \
                af[mt][1] = tf32cvt(As[m + 8][k]);                             \
                af[mt][2] = tf32cvt(As[m][k + 4]);                             \
                af[mt][3] = tf32cvt(As[m + 8][k + 4]);                         \
            }                                                                  \
            _Pragma("unroll")                                                  \
            for (int nt = 0; nt < 4; nt++) {                                   \
                int n = wc * 32 + nt * 8 + gid;                                \
                int k = kb + q4;                                               \
                bf[nt][0] = tf32cvt(Bs[k][n]);                                 \
                bf[nt][1] = tf32cvt(Bs[k + 4][n]);                             \
            }                                                                  \
            _Pragma("unroll")                                                  \
            for (int mt = 0; mt < 4; mt++)                                     \
                _Pragma("unroll")                                              \
                for (int nt = 0; nt < 4; nt++)                                 \
                    mma_tf32(acc[mt][nt], af[mt], bf[nt]);                     \
        }                                                                      \
        __syncthreads();                                                       \
    }

// QKV projection: C = x @ w_qkv + b_qkv, scattered into g_q/g_k/g_v (B,H,S,Hd)
__global__ void __launch_bounds__(256) mma_qkv(
    const float* __restrict__ A, const float* __restrict__ Bm,
    const float* __restrict__ bias)
{
    GEMM_CORE(A, Bm, DIM, 3*DIM)

    #pragma unroll
    for (int mt = 0; mt < 4; mt++) {
        #pragma unroll
        for (int nt = 0; nt < 4; nt++) {
            #pragma unroll
            for (int e = 0; e < 4; e++) {
                int row = row0 + wr*64 + mt*16 + gid + (e >> 1) * 8;
                int col = col0 + wc*32 + nt*8 + 2*q4 + (e & 1);
                float v = acc[mt][nt][e] + bias[col];
                int b  = row >> 11;
                int s  = row & 2047;
                int three = col >> 10;
                int rem   = col & 1023;
                int h     = rem >> 6;
                int hd    = rem & 63;
                size_t dst = ((size_t)(b*NH + h)*SEQ + s)*HD + hd;
                if (three == 0)      g_q[dst] = v;
                else if (three == 1) g_k[dst] = v;
                else                 g_v[dst] = v;
            }
        }
    }
}

// Output projection: d_out = g_attn @ w_out + b_out
__global__ void __launch_bounds__(256) mma_out(
    const float* __restrict__ Bm, const float* __restrict__ bias,
    float* __restrict__ C)
{
    const float* A = g_attn;
    GEMM_CORE(A, Bm, DIM, DIM)

    #pragma unroll
    for (int mt = 0; mt < 4; mt++) {
        #pragma unroll
        for (int nt = 0; nt < 4; nt++) {
            #pragma unroll
            for (int e = 0; e < 4; e++) {
                int row = row0 + wr*64 + mt*16 + gid + (e >> 1) * 8;
                int col = col0 + wc*32 + nt*8 + 2*q4 + (e & 1);
                C[(size_t)row*DIM + col] = acc[mt][nt][e] + bias[col];
            }
        }
    }
}

// ---------------------------------------------------------------------------
// Fused flash attention with tf32 mma. Block = 64 queries of one (b,h),
// 128 threads = 4 warps; warp w owns q-rows [w*16, w*16+16).
// Per key tile of 64: S = Q@K^T via mma, online softmax in C-fragment
// registers, P staged through per-warp SMEM, O += P@V via mma.
// ---------------------------------------------------------------------------
#define QT 64
#define KT 64
#define FPITCH 68   // 64 + 4 -> conflict-free fragment loads

__global__ void __launch_bounds__(128) attn_kernel()
{
    extern __shared__ float sm[];
    float (*Qs)[FPITCH] = (float (*)[FPITCH])sm;                 // [64][68]
    float (*Ks)[FPITCH] = (float (*)[FPITCH])(sm + QT*FPITCH);   // [64][68]
    float (*Vs)[FPITCH] = (float (*)[FPITCH])(sm + 2*QT*FPITCH); // [64][68]
    float (*Ps)[FPITCH] = (float (*)[FPITCH])(sm + 3*QT*FPITCH); // [64][68]

    int tid  = threadIdx.x;
    int lane = tid & 31;
    int w    = tid >> 5;     // 0..3
    int gid  = lane >> 2;    // 0..7
    int q4   = lane & 3;     // 0..3

    int b  = blockIdx.z;
    int h  = blockIdx.y;
    int q0 = blockIdx.x * QT;

    const float* qptr = g_q + ((size_t)(b*NH + h)*SEQ)*HD;
    const float* kptr = g_k + ((size_t)(b*NH + h)*SEQ)*HD;
    const float* vptr = g_v + ((size_t)(b*NH + h)*SEQ)*HD;

    // load Q tile (scaled): 64x64 = 1024 float4 / 128 thr = 8 each
    #pragma unroll
    for (int it = 0; it < 8; it++) {
        int e  = tid + it*128;
        int r  = e >> 4;
        int c4 = (e & 15) * 4;
        float4 v = *(const float4*)&qptr[(size_t)(q0 + r)*HD + c4];
        Qs[r][c4+0] = v.x * SCALE;
        Qs[r][c4+1] = v.y * SCALE;
        Qs[r][c4+2] = v.z * SCALE;
        Qs[r][c4+3] = v.w * SCALE;
    }

    float m_a = -INFINITY, m_b = -INFINITY;
    float l_a = 0.f, l_b = 0.f;
    float O[8][4];
    #pragma unroll
    for (int dt = 0; dt < 8; dt++)
        #pragma unroll
        for (int e = 0; e < 4; e++) O[dt][e] = 0.f;

    __syncthreads();

    for (int kt = 0; kt < SEQ; kt += KT) {
        // load K/V tiles
        #pragma unroll
        for (int it = 0; it < 8; it++) {
            int e  = tid + it*128;
            int r  = e >> 4;
            int c4 = (e & 15) * 4;
            float4 kv = *(const float4*)&kptr[(size_t)(kt + r)*HD + c4];
            *(float4*)&Ks[r][c4] = kv;
            float4 vv = *(const float4*)&vptr[(size_t)(kt + r)*HD + c4];
            *(float4*)&Vs[r][c4] = vv;
        }
        __syncthreads();

        // S = Q @ K^T   (warp: 16 rows x 64 keys -> 8 n-tiles)
        float S[8][4];
        #pragma unroll
        for (int nt = 0; nt < 8; nt++)
            #pragma unroll
            for (int e = 0; e < 4; e++) S[nt][e] = 0.f;

        #pragma unroll
        for (int kk = 0; kk < 8; kk++) {
            int d = kk*8 + q4;
            uint32_t af[4];
            int m = w*16 + gid;
            af[0] = tf32cvt(Qs[m][d]);
            af[1] = tf32cvt(Qs[m+8][d]);
            af[2] = tf32cvt(Qs[m][d+4]);
            af[3] = tf32cvt(Qs[m+8][d+4]);
            uint32_t bf[8][2];
            #pragma unroll
            for (int nt = 0; nt < 8; nt++) {
                bf[nt][0] = tf32cvt(Ks[nt*8 + gid][d]);
                bf[nt][1] = tf32cvt(Ks[nt*8 + gid][d+4]);
            }
            #pragma unroll
            for (int nt = 0; nt < 8; nt++)
                mma_tf32(S[nt], af, bf[nt]);
        }

        // online softmax. Thread owns rows r_a=gid, r_b=gid+8 (warp-local);
        // row values: S[nt][0..1] (row a), S[nt][2..3] (row b).
        {
            float ma = S[0][0], mb = S[0][2];
            #pragma unroll
            for (int nt = 0; nt < 8; nt++) {
                ma = fmaxf(ma, fmaxf(S[nt][0], S[nt][1]));
                mb = fmaxf(mb, fmaxf(S[nt][2], S[nt][3]));
            }
            #pragma unroll
            for (int off = 1; off <= 2; off <<= 1) {
                ma = fmaxf(ma, __shfl_xor_sync(0xffffffffu, ma, off));
                mb = fmaxf(mb, __shfl_xor_sync(0xffffffffu, mb, off));
            }
            float mna = fmaxf(m_a, ma);
            float mnb = fmaxf(m_b, mb);
            float alpha_a = __expf(m_a - mna);
            float alpha_b = __expf(m_b - mnb);
            float sa = 0.f, sb = 0.f;
            #pragma unroll
            for (int nt = 0; nt < 8; nt++) {
                S[nt][0] = __expf(S[nt][0] - mna);
                S[nt][1] = __expf(S[nt][1] - mna);
                S[nt][2] = __expf(S[nt][2] - mnb);
                S[nt][3] = __expf(S[nt][3] - mnb);
                sa += S[nt][0] + S[nt][1];
                sb += S[nt][2] + S[nt][3];
            }
            #pragma unroll
            for (int off = 1; off <= 2; off <<= 1) {
                sa += __shfl_xor_sync(0xffffffffu, sa, off);
                sb += __shfl_xor_sync(0xffffffffu, sb, off);
            }
            l_a = l_a * alpha_a + sa;
            l_b = l_b * alpha_b + sb;
            m_a = mna; m_b = mnb;
            #pragma unroll
            for (int dt = 0; dt < 8; dt++) {
                O[dt][0] *= alpha_a; O[dt][1] *= alpha_a;
                O[dt][2] *= alpha_b; O[dt][3] *= alpha_b;
            }
        }

        // stage P into this warp's SMEM strip (rows w*16..w*16+15)
        #pragma unroll
        for (int nt = 0; nt < 8; nt++) {
            int col = nt*8 + 2*q4;
            Ps[w*16 + gid][col]     = S[nt][0];
            Ps[w*16 + gid][col+1]   = S[nt][1];
            Ps[w*16 + gid+8][col]   = S[nt][2];
            Ps[w*16 + gid+8][col+1] = S[nt][3];
        }
        __syncwarp();

        // O += P @ V
        #pragma unroll
        for (int kk = 0; kk < 8; kk++) {
            int kkey = kk*8 + q4;
            uint32_t af[4];
            int m = w*16 + gid;
            af[0] = tf32cvt(Ps[m][kkey]);
            af[1] = tf32cvt(Ps[m+8][kkey]);
            af[2] = tf32cvt(Ps[m][kkey+4]);
            af[3] = tf32cvt(Ps[m+8][kkey+4]);
            uint32_t bf[8][2];
            #pragma unroll
            for (int dt = 0; dt < 8; dt++) {
                bf[dt][0] = tf32cvt(Vs[kkey][dt*8 + gid]);
                bf[dt][1] = tf32cvt(Vs[kkey+4][dt*8 + gid]);
            }
            #pragma unroll
            for (int dt = 0; dt < 8; dt++)
                mma_tf32(O[dt], af, bf[dt]);
        }
        __syncthreads();   // before next tile overwrites Ks/Vs
    }

    // write normalized output in (B,S,D) layout for the final GEMM
    float inv_a = 1.f / l_a;
    float inv_b = 1.f / l_b;
    size_t rowbase_a = ((size_t)b*SEQ + q0 + w*16 + gid)*DIM + h*HD;
    size_t rowbase_b = ((size_t)b*SEQ + q0 + w*16 + gid + 8)*DIM + h*HD;
    #pragma unroll
    for (int dt = 0; dt < 8; dt++) {
        int col = dt*8 + 2*q4;
        g_attn[rowbase_a + col]     = O[dt][0] * inv_a;
        g_attn[rowbase_a + col + 1] = O[dt][1] * inv_a;
        g_attn[rowbase_b + col]     = O[dt][2] * inv_b;
        g_attn[rowbase_b + col + 1] = O[dt][3] * inv_b;
    }
}

// ---------------------------------------------------------------------------
extern "C" void kernel_launch(void* const* d_in, const int* in_sizes, int n_in,
                              void* d_out, int out_size)
{
    const float* x      = (const float*)d_in[0];
    const float* w_qkv  = (const float*)d_in[1];
    const float* b_qkv  = (const float*)d_in[2];
    const float* w_out  = (const float*)d_in[3];
    const float* b_out  = (const float*)d_in[4];
    float* out = (float*)d_out;

    // 1) QKV projection + scatter
    dim3 g1(3*DIM / GBN, MTOK / GBM);
    mma_qkv<<<g1, 256>>>(x, w_qkv, b_qkv);

    // 2) fused attention
    size_t smem = (size_t)4 * QT * FPITCH * sizeof(float);  // 69632 B
    cudaFuncSetAttribute(attn_kernel,
                         cudaFuncAttributeMaxDynamicSharedMemorySize, (int)smem);
    dim3 g2(SEQ / QT, NH, BATCH);
    attn_kernel<<<g2, 128, smem>>>();

    // 3) output projection
    dim3 g3(DIM / GBN, MTOK / GBM);
    mma_out<<<g3, 256>>>(w_out, b_out, out);
}